// round 3
// baseline (speedup 1.0000x reference)
#include <cuda_runtime.h>
#include <math.h>
#include <float.h>

// ---------------- problem constants ----------------
#define NIMG 4
#define H 128
#define W 128
#define P 11
#define KSEL 16
#define WIN 65
#define V 32
#define S 3
#define HREF 40
#define WREF 40
#define LGRP (HREF*WREF)
#define WP 118              // H - P + 1
#define NPIX (H*W)
#define NPATCH (P*P)
#define NOFF 65
#define E_REG 30.25f
#define DE_REG 151.25f

// ---------------- device scratch ----------------
// [n][gh][dy][dx][gw] : 4*40*65*65*40 floats = 27.04M floats (~108MB)
__device__ float g_ssd[(size_t)NIMG * HREF * NOFF * NOFF * WREF];
__device__ int   g_ind[NIMG * LGRP * KSEL];
__device__ float g_num[NIMG * NPIX];
__device__ float g_den[NIMG * NPIX];

// ---------------- zero accumulators ----------------
__global__ void zero_kernel() {
    int i = blockIdx.x * blockDim.x + threadIdx.x;
    if (i < NIMG * NPIX) { g_num[i] = 0.f; g_den[i] = 0.f; }
}

// ---------------- stage 1: SSD via separable box sums ----------------
// grid (NOFF, NIMG): one CTA per (n, dy). 256 threads = 2 halves x 128 columns,
// each half handles one dx per outer iteration.
__global__ __launch_bounds__(256) void ssd_kernel(const float* __restrict__ y) {
    __shared__ float CC[2][HREF][W];   // 40KB

    const int dyb  = blockIdx.x;
    const int n    = blockIdx.y;
    const int half = threadIdx.x >> 7;
    const int c    = threadIdx.x & 127;
    const int oy   = dyb - V;
    const float* img = y + n * NPIX;

    for (int it = 0; it < 33; it++) {
        const int dx = it * 2 + half;
        const bool dxok = (dx < NOFF);
        const int ox = dx - V;
        const int cc2 = min(max(c + ox, 0), W - 1);

        // phase A: sliding 11-row column sums, emitted at stride 3
        {
            float ring[P];
            float run = 0.f;
            int head = 0;
#pragma unroll 1
            for (int r = 0; r < P; r++) {
                int rs = min(max(r + oy, 0), H - 1);
                float a = __ldg(&img[r * W + c]);
                float b = __ldg(&img[rs * W + cc2]);
                float d = (a - b) * (a - b);
                ring[r] = d; run += d;
            }
            CC[half][0][c] = run;
#pragma unroll 1
            for (int gh = 1; gh < HREF; gh++) {
#pragma unroll
                for (int step = 0; step < S; step++) {
                    int r = 3 * gh + 8 + step;      // rows 11..127 enter
                    int rs = min(max(r + oy, 0), H - 1);
                    float a = __ldg(&img[r * W + c]);
                    float b = __ldg(&img[rs * W + cc2]);
                    float d = (a - b) * (a - b);
                    run += d - ring[head];
                    ring[head] = d;
                    head = (head + 1 == P) ? 0 : head + 1;
                }
                CC[half][gh][c] = run;
            }
        }
        __syncthreads();

        // phase B: horizontal 11-sums + masking + store
        if (dxok) {
            for (int idx = c; idx < LGRP; idx += 128) {
                int gh = idx / WREF, gw = idx % WREF;
                bool rok = (unsigned)(3 * gh + oy) <= (unsigned)(H - P);
                bool cok = (unsigned)(3 * gw + ox) <= (unsigned)(W - P);
                float s = FLT_MAX;
                if (rok && cok) {
                    s = 0.f;
                    const float* row = &CC[half][gh][3 * gw];
#pragma unroll
                    for (int b = 0; b < P; b++) s += row[b];
                    if (oy == 0 && ox == 0) s = -FLT_MAX;
                }
                g_ssd[(((size_t)(n * HREF + gh) * NOFF + dyb) * NOFF + dx) * WREF + gw] = s;
            }
        }
        __syncthreads();
    }
}

// ---------------- stage 2: streaming top-16 per group ----------------
// one CTA per (n, gh); lane gw < 40 owns one group.
__global__ __launch_bounds__(64) void topk_kernel() {
    const int gh = blockIdx.x % HREF;
    const int n  = blockIdx.x / HREF;
    const int gw = threadIdx.x;
    if (gw >= WREF) return;

    const float* base = g_ssd + (size_t)(n * HREF + gh) * NOFF * NOFF * WREF + gw;

    float vals[KSEL];
    int   idxs[KSEL];
#pragma unroll
    for (int j = 0; j < KSEL; j++) { vals[j] = FLT_MAX; idxs[j] = 0; }
    float cmax = FLT_MAX; int am = 0;

#pragma unroll 1
    for (int o = 0; o < NOFF * NOFF; o++) {
        float v = __ldg(&base[(size_t)o * WREF]);
        if (v < cmax) {
            vals[am] = v; idxs[am] = o;
            cmax = vals[0]; am = 0;
#pragma unroll
            for (int j = 1; j < KSEL; j++)
                if (vals[j] > cmax) { cmax = vals[j]; am = j; }
        }
    }

    int* out = &g_ind[((n * LGRP) + gh * WREF + gw) * KSEL];
#pragma unroll
    for (int j = 0; j < KSEL; j++) {
        int o = idxs[j];
        int dy = o / NOFF, dx = o % NOFF;
        out[j] = (3 * gh + dy - V) * WP + (3 * gw + dx - V);
    }
}

// ---------------- gather + denoise + scatter ----------------
__global__ __launch_bounds__(128) void denoise_kernel(const float* __restrict__ y) {
    __shared__ float Ys[KSEL][128];
    __shared__ float Qs[KSEL][KSEL + 1];
    __shared__ float Qi[KSEL][KSEL + 1];
    __shared__ float Th[KSEL][KSEL + 1];
    __shared__ float wgt[KSEL];
    __shared__ float q1[KSEL];
    __shared__ float q2s;
    __shared__ int   pr[KSEL], pc[KSEL];

    const int g = blockIdx.x;
    const int n = g / LGRP;
    const int tid = threadIdx.x;
    const float* img = y + n * NPIX;

    if (tid < KSEL) {
        int idx = g_ind[g * KSEL + tid];
        pr[tid] = idx / WP;
        pc[tid] = idx % WP;
    }
    __syncthreads();

    for (int t = tid; t < KSEL * 128; t += 128) {
        int i = t >> 7, e = t & 127;
        float v = 0.f;
        if (e < NPATCH) {
            int a = e / P, b = e % P;
            v = img[(pr[i] + a) * W + pc[i] + b];
        }
        Ys[i][e] = v;
    }
    __syncthreads();

    for (int t = tid; t < KSEL * KSEL; t += 128) {
        int i = t / KSEL, j = t % KSEL;
        const float4* yi = reinterpret_cast<const float4*>(Ys[i]);
        const float4* yj = reinterpret_cast<const float4*>(Ys[j]);
        float s = 0.f;
#pragma unroll
        for (int q = 0; q < 32; q++) {
            float4 u = yi[q], v = yj[q];
            s += u.x * v.x + u.y * v.y + u.z * v.z + u.w * v.w;
        }
        if (i == j) s += E_REG;
        Qs[i][j] = s;
    }
    __syncthreads();

    if (tid < 32) {
        int lane = tid;
        for (int j = 0; j < KSEL; j++) {
            if (lane == 0) Qs[j][j] = sqrtf(Qs[j][j]);
            __syncwarp();
            float dj = Qs[j][j];
            if (lane > j && lane < KSEL) Qs[lane][j] /= dj;
            __syncwarp();
            if (lane > j && lane < KSEL) {
                float lij = Qs[lane][j];
                for (int m = j + 1; m <= lane; m++) Qs[lane][m] -= lij * Qs[m][j];
            }
            __syncwarp();
        }
        if (lane < KSEL) {
            float z[KSEL];
            for (int i = 0; i < KSEL; i++) {
                float s = (i == lane) ? 1.f : 0.f;
                for (int j = 0; j < i; j++) s -= Qs[i][j] * z[j];
                z[i] = s / Qs[i][i];
            }
            for (int i = KSEL - 1; i >= 0; i--) {
                float s = z[i];
                for (int j = i + 1; j < KSEL; j++) s -= Qs[j][i] * z[j];
                z[i] = s / Qs[i][i];
            }
            for (int i = 0; i < KSEL; i++) Qi[i][lane] = z[i];
        }
    }
    __syncthreads();

    if (tid < KSEL) {
        float s = 0.f;
        for (int j = 0; j < KSEL; j++) s += Qi[tid][j];
        q1[tid] = s;
    }
    __syncthreads();
    if (tid == 0) {
        float s = 0.f;
        for (int i = 0; i < KSEL; i++) s += q1[i];
        q2s = s;
    }
    __syncthreads();
    for (int t = tid; t < KSEL * KSEL; t += 128) {
        int i = t / KSEL, j = t % KSEL;
        Th[i][j] = ((i == j) ? 1.f : 0.f) - (Qi[i][j] - q1[i] * q1[j] / q2s) * DE_REG;
    }
    __syncthreads();
    if (tid < KSEL) {
        float s = 0.f;
        for (int j = 0; j < KSEL; j++) s += Th[tid][j] * Th[tid][j];
        s = fminf(fmaxf(s, 1.f / (float)KSEL), 1.f);
        wgt[tid] = 1.f / s;
    }
    __syncthreads();

    float* numI = g_num + n * NPIX;
    float* denI = g_den + n * NPIX;
    for (int t = tid; t < KSEL * NPATCH; t += 128) {
        int i = t / NPATCH, e = t % NPATCH;
        float s = 0.f;
#pragma unroll
        for (int j = 0; j < KSEL; j++) s += Th[i][j] * Ys[j][e];
        float wv = wgt[i];
        int a = e / P, b = e % P;
        int pix = (pr[i] + a) * W + pc[i] + b;
        atomicAdd(&numI[pix], s * wv);
        atomicAdd(&denI[pix], wv);
    }
}

// ---------------- final divide ----------------
__global__ void div_kernel(float* __restrict__ out) {
    int i = blockIdx.x * blockDim.x + threadIdx.x;
    if (i < NIMG * NPIX) out[i] = g_num[i] / g_den[i];
}

extern "C" void kernel_launch(void* const* d_in, const int* in_sizes, int n_in,
                              void* d_out, int out_size) {
    const float* y = (const float*)d_in[0];
    float* out = (float*)d_out;

    zero_kernel<<<(NIMG * NPIX + 255) / 256, 256>>>();

    dim3 sgrid(NOFF, NIMG);
    ssd_kernel<<<sgrid, 256>>>(y);

    topk_kernel<<<NIMG * HREF, 64>>>();

    denoise_kernel<<<NIMG * LGRP, 128>>>(y);

    div_kernel<<<(NIMG * NPIX + 255) / 256, 256>>>(out);
}

// round 4
// speedup vs baseline: 2.1381x; 2.1381x over previous
#include <cuda_runtime.h>
#include <math.h>
#include <float.h>

// ---------------- problem constants ----------------
#define NIMG 4
#define H 128
#define W 128
#define P 11
#define KSEL 16
#define WIN 65
#define V 32
#define S 3
#define HREF 40
#define WREF 40
#define LGRP (HREF*WREF)
#define WP 118              // H - P + 1
#define NPIX (H*W)
#define NPATCH (P*P)
#define NOFF 65
#define E_REG 30.25f
#define DE_REG 151.25f

// ---------------- device scratch ----------------
// [n][gh][dy][dx][gw]
__device__ float g_ssd[(size_t)NIMG * HREF * NOFF * NOFF * WREF];
__device__ int   g_ind[NIMG * LGRP * KSEL];
__device__ float g_num[NIMG * NPIX];
__device__ float g_den[NIMG * NPIX];

// ---------------- zero accumulators ----------------
__global__ void zero_kernel() {
    int i = blockIdx.x * blockDim.x + threadIdx.x;
    if (i < NIMG * NPIX) { g_num[i] = 0.f; g_den[i] = 0.f; }
}

// ---------------- stage 1: SSD via separable box sums (all-static regs) ----
// grid (NOFF, NIMG): one CTA per (n, dy). 256 threads = 2 halves x 128 cols.
__global__ __launch_bounds__(256) void ssd_kernel(const float* __restrict__ y) {
    __shared__ float CC[2][HREF][W];   // 40KB

    const int dyb  = blockIdx.x;
    const int n    = blockIdx.y;
    const int half = threadIdx.x >> 7;
    const int c    = threadIdx.x & 127;
    const int oy   = dyb - V;
    const float* img = y + n * NPIX;

    for (int it = 0; it < 33; it++) {
        const int dx = it * 2 + half;
        const bool dxok = (dx < NOFF);
        const int ox = dx - V;
        const int cc2 = min(max(c + ox, 0), W - 1);

#define DVAL(r) ({ int rs_ = min(max((r) + oy, 0), H - 1);               \
                   float a_ = __ldg(&img[(r) * W + c]);                  \
                   float b_ = __ldg(&img[rs_ * W + cc2]);                \
                   float t_ = a_ - b_; t_ * t_; })

        // phase A: CC[gh] = sum_{r=3gh..3gh+10} D(r), static sliding
        {
            float T1, T2, T3, da, db;
            {
                float T0 = DVAL(0) + DVAL(1) + DVAL(2);
                T1 = DVAL(3) + DVAL(4) + DVAL(5);
                T2 = DVAL(6) + DVAL(7) + DVAL(8);
                da = DVAL(9); db = DVAL(10);
                CC[half][0][c] = T0 + T1 + T2 + da + db;
            }
#pragma unroll 1
            for (int gh = 1; gh < HREF; gh++) {
                float dn = DVAL(3 * gh + 8);
                T3 = da + db + dn;
                da = DVAL(3 * gh + 9);
                db = DVAL(3 * gh + 10);
                CC[half][gh][c] = T1 + T2 + T3 + da + db;
                T1 = T2; T2 = T3;
            }
        }
#undef DVAL
        __syncthreads();

        // phase B: horizontal 11-sums + masking + store
        if (dxok) {
            for (int idx = c; idx < LGRP; idx += 128) {
                int gh = idx / WREF, gw = idx % WREF;
                bool rok = (unsigned)(3 * gh + oy) <= (unsigned)(H - P);
                bool cok = (unsigned)(3 * gw + ox) <= (unsigned)(W - P);
                float s = FLT_MAX;
                if (rok && cok) {
                    s = 0.f;
                    const float* row = &CC[half][gh][3 * gw];
#pragma unroll
                    for (int b = 0; b < P; b++) s += row[b];
                    if (oy == 0 && ox == 0) s = -FLT_MAX;
                }
                g_ssd[(((size_t)(n * HREF + gh) * NOFF + dyb) * NOFF + dx) * WREF + gw] = s;
            }
        }
        __syncthreads();
    }
}

// ---------------- stage 2: 4-way split streaming top-16 per group ----------
// one CTA per (n, gh); 160 threads: gw = t%40, quarter q = t/40.
__global__ __launch_bounds__(160) void topk_kernel() {
    __shared__ float sv[WREF][4 * KSEL + 1];
    __shared__ int   si[WREF][4 * KSEL + 1];

    const int gh = blockIdx.x % HREF;
    const int n  = blockIdx.x / HREF;
    const int t  = threadIdx.x;
    const int gw = t % WREF;
    const int q  = t / WREF;

    const float* base = g_ssd + (size_t)(n * HREF + gh) * NOFF * NOFF * WREF + gw;

    float vals[KSEL];
    int   idxs[KSEL];
#pragma unroll
    for (int j = 0; j < KSEL; j++) { vals[j] = FLT_MAX; idxs[j] = 0; }
    float cmax = FLT_MAX; int am = 0;

    const int o0 = q * 1057;
    const int o1 = min(NOFF * NOFF, o0 + 1057);
#pragma unroll 4
    for (int o = o0; o < o1; o++) {
        float v = __ldg(&base[(size_t)o * WREF]);
        if (v < cmax) {
            vals[am] = v; idxs[am] = o;
            cmax = vals[0]; am = 0;
#pragma unroll
            for (int j = 1; j < KSEL; j++)
                if (vals[j] > cmax) { cmax = vals[j]; am = j; }
        }
    }
#pragma unroll
    for (int j = 0; j < KSEL; j++) {
        sv[gw][q * KSEL + j] = vals[j];
        si[gw][q * KSEL + j] = idxs[j];
    }
    __syncthreads();

    // merge: 16 smallest of the 64 partials (one thread per gw)
    if (q == 0) {
        int* out = &g_ind[((n * LGRP) + gh * WREF + gw) * KSEL];
        for (int sel = 0; sel < KSEL; sel++) {
            float bv = FLT_MAX; int bslot = 0;
            for (int m = 0; m < 4 * KSEL; m++) {
                float v = sv[gw][m];
                if (v < bv) { bv = v; bslot = m; }
            }
            int o = si[gw][bslot];
            sv[gw][bslot] = FLT_MAX;
            int dy = o / NOFF, dxo = o % NOFF;
            out[sel] = (3 * gh + dy - V) * WP + (3 * gw + dxo - V);
        }
    }
}

// ---------------- gather + denoise + scatter ----------------
__global__ __launch_bounds__(128, 8) void denoise_kernel(const float* __restrict__ y) {
    __shared__ float Ys[KSEL][128];
    __shared__ float Qs[KSEL][KSEL + 1];
    __shared__ float Qi[KSEL][KSEL + 1];
    __shared__ float Th[KSEL][KSEL + 1];
    __shared__ float wgt[KSEL];
    __shared__ float q1[KSEL];
    __shared__ float q2s;
    __shared__ int   pr[KSEL], pc[KSEL];

    const int g = blockIdx.x;
    const int n = g / LGRP;
    const int tid = threadIdx.x;
    const float* img = y + n * NPIX;

    if (tid < KSEL) {
        int idx = g_ind[g * KSEL + tid];
        pr[tid] = idx / WP;
        pc[tid] = idx % WP;
    }
    __syncthreads();

    // gather (zero-pad cols 121..127)
    for (int t = tid; t < KSEL * 128; t += 128) {
        int i = t >> 7, e = t & 127;
        float v = 0.f;
        if (e < NPATCH) {
            int a = e / P, b = e % P;
            v = img[(pr[i] + a) * W + pc[i] + b];
        }
        Ys[i][e] = v;
    }
    __syncthreads();

    // Q = Y Y^T + E I (symmetric: compute i<=j, mirror)
    for (int t = tid; t < KSEL * KSEL; t += 128) {
        int i = t / KSEL, j = t % KSEL;
        if (i <= j) {
            const float4* yi = reinterpret_cast<const float4*>(Ys[i]);
            const float4* yj = reinterpret_cast<const float4*>(Ys[j]);
            float s = 0.f;
#pragma unroll 4
            for (int q = 0; q < 32; q++) {
                float4 u = yi[q], v = yj[q];
                s += u.x * v.x + u.y * v.y + u.z * v.z + u.w * v.w;
            }
            if (i == j) s += E_REG;
            Qs[i][j] = s;
            Qs[j][i] = s;
        }
    }
    __syncthreads();

    // Cholesky + inverse on warp 0
    if (tid < 32) {
        int lane = tid;
        for (int j = 0; j < KSEL; j++) {
            if (lane == 0) Qs[j][j] = sqrtf(Qs[j][j]);
            __syncwarp();
            float dj = Qs[j][j];
            if (lane > j && lane < KSEL) Qs[lane][j] /= dj;
            __syncwarp();
            if (lane > j && lane < KSEL) {
                float lij = Qs[lane][j];
                for (int m = j + 1; m <= lane; m++) Qs[lane][m] -= lij * Qs[m][j];
            }
            __syncwarp();
        }
        if (lane < KSEL) {
            float z[KSEL];
            for (int i = 0; i < KSEL; i++) {
                float s = (i == lane) ? 1.f : 0.f;
                for (int j = 0; j < i; j++) s -= Qs[i][j] * z[j];
                z[i] = s / Qs[i][i];
            }
            for (int i = KSEL - 1; i >= 0; i--) {
                float s = z[i];
                for (int j = i + 1; j < KSEL; j++) s -= Qs[j][i] * z[j];
                z[i] = s / Qs[i][i];
            }
            for (int i = 0; i < KSEL; i++) Qi[i][lane] = z[i];
        }
    }
    __syncthreads();

    if (tid < KSEL) {
        float s = 0.f;
        for (int j = 0; j < KSEL; j++) s += Qi[tid][j];
        q1[tid] = s;
    }
    __syncthreads();
    if (tid == 0) {
        float s = 0.f;
        for (int i = 0; i < KSEL; i++) s += q1[i];
        q2s = s;
    }
    __syncthreads();
    for (int t = tid; t < KSEL * KSEL; t += 128) {
        int i = t / KSEL, j = t % KSEL;
        Th[i][j] = ((i == j) ? 1.f : 0.f) - (Qi[i][j] - q1[i] * q1[j] / q2s) * DE_REG;
    }
    __syncthreads();
    if (tid < KSEL) {
        float s = 0.f;
        for (int j = 0; j < KSEL; j++) s += Th[tid][j] * Th[tid][j];
        s = fminf(fmaxf(s, 1.f / (float)KSEL), 1.f);
        wgt[tid] = 1.f / s;
    }
    __syncthreads();

    // X_hat = theta @ Y (float4 over pixels) ; weighted scatter
    float* numI = g_num + n * NPIX;
    float* denI = g_den + n * NPIX;
    for (int t = tid; t < KSEL * 32; t += 128) {
        int i = t >> 5, eq = t & 31;
        int e = eq * 4;
        if (e < NPATCH) {
            float4 acc = make_float4(0.f, 0.f, 0.f, 0.f);
#pragma unroll
            for (int j = 0; j < KSEL; j++) {
                float th = Th[i][j];
                float4 v = *reinterpret_cast<const float4*>(&Ys[j][e]);
                acc.x += th * v.x; acc.y += th * v.y;
                acc.z += th * v.z; acc.w += th * v.w;
            }
            float wv = wgt[i];
            float res[4] = {acc.x, acc.y, acc.z, acc.w};
#pragma unroll
            for (int u = 0; u < 4; u++) {
                int ee = e + u;
                if (ee < NPATCH) {
                    int a = ee / P, b = ee % P;
                    int pix = (pr[i] + a) * W + pc[i] + b;
                    atomicAdd(&numI[pix], res[u] * wv);
                    atomicAdd(&denI[pix], wv);
                }
            }
        }
    }
}

// ---------------- final divide ----------------
__global__ void div_kernel(float* __restrict__ out) {
    int i = blockIdx.x * blockDim.x + threadIdx.x;
    if (i < NIMG * NPIX) out[i] = g_num[i] / g_den[i];
}

extern "C" void kernel_launch(void* const* d_in, const int* in_sizes, int n_in,
                              void* d_out, int out_size) {
    const float* y = (const float*)d_in[0];
    float* out = (float*)d_out;

    zero_kernel<<<(NIMG * NPIX + 255) / 256, 256>>>();

    dim3 sgrid(NOFF, NIMG);
    ssd_kernel<<<sgrid, 256>>>(y);

    topk_kernel<<<NIMG * HREF, 160>>>();

    denoise_kernel<<<NIMG * LGRP, 128>>>(y);

    div_kernel<<<(NIMG * NPIX + 255) / 256, 256>>>(out);
}

// round 5
// speedup vs baseline: 5.2806x; 2.4697x over previous
#include <cuda_runtime.h>
#include <math.h>
#include <float.h>

// ---------------- problem constants ----------------
#define NIMG 4
#define H 128
#define W 128
#define P 11
#define KSEL 16
#define WIN 65
#define V 32
#define S 3
#define HREF 40
#define WREF 40
#define LGRP (HREF*WREF)
#define WP 118              // H - P + 1
#define NPIX (H*W)
#define NPATCH (P*P)
#define NOFF 65
#define NSLC 4              // oy slices per (n,gh)
#define NQ 6                // ox slices in phase 2
#define E_REG 30.25f
#define DE_REG 151.25f

// ---------------- device scratch ----------------
__device__ float g_pv[NIMG * HREF * NSLC * WREF * KSEL];   // partial top-16 values
__device__ int   g_pi[NIMG * HREF * NSLC * WREF * KSEL];   // partial top-16 packed offsets
__device__ int   g_ind[NIMG * LGRP * KSEL];
__device__ float g_num[NIMG * NPIX];
__device__ float g_den[NIMG * NPIX];

// ---------------- zero accumulators ----------------
__global__ void zero_kernel() {
    int i = blockIdx.x * blockDim.x + threadIdx.x;
    if (i < NIMG * NPIX) { g_num[i] = 0.f; g_den[i] = 0.f; }
}

// ---------------- fused block matching: SSD band + streaming top-16 -------
// grid: NIMG*HREF*NSLC CTAs, 256 threads.
// CTA handles (n, gh, oy-slice). Per oy: stage shifted rows -> column sums
// CS[65][128] -> horizontal sums + per-(gw,slice) register top-16.
__global__ __launch_bounds__(256) void bm_kernel(const float* __restrict__ y) {
    __shared__ float CS[NOFF][W];     // 33.3KB column sums (reused as merge buf)
    __shared__ float BR[P][W];        // 5.6KB shifted row strip

    const int blk = blockIdx.x;
    const int s   = blk % NSLC;
    const int gid = blk / NSLC;
    const int gh  = gid % HREF;
    const int n   = gid / HREF;
    const int t   = threadIdx.x;
    const int c   = t & 127;
    const int half = t >> 7;
    const float* img = y + n * NPIX;

    // reference band rows in registers (both halves hold the same)
    float a[P];
#pragma unroll
    for (int r = 0; r < P; r++) a[r] = __ldg(&img[(3 * gh + r) * W + c]);

    // valid oy range for this gh, sliced NSLC ways
    const int oylo = max(-V, -3 * gh);
    const int oyhi = min(V, (H - P) - 3 * gh);
    const int cnt  = oyhi - oylo + 1;
    const int s0   = oylo + (cnt * s) / NSLC;
    const int s1   = oylo + (cnt * (s + 1)) / NSLC;

    // per-thread streaming top-16 (phase-2 role: gw = t%40, q = t/40)
    const int gw = t % WREF;
    const int q  = t / WREF;          // 0..5 active (t<240)
    float vals[KSEL];
    int   idxs[KSEL];
#pragma unroll
    for (int j = 0; j < KSEL; j++) { vals[j] = FLT_MAX; idxs[j] = 0; }
    float cmax = FLT_MAX; int am = 0;

    const int ox0p1 = half * 33;                 // phase-1 ox slice
    const int ox1p1 = min(NOFF, ox0p1 + 33);

    for (int oy = s0; oy < s1; oy++) {
        // stage shifted rows
        for (int i = t; i < P * W; i += 256) {
            int r = i >> 7, cc = i & 127;
            int rs = min(max(3 * gh + r + oy, 0), H - 1);
            BR[r][cc] = __ldg(&img[rs * W + cc]);
        }
        __syncthreads();

        // phase 1: column sums for all 65 ox
        for (int oxi = ox0p1; oxi < ox1p1; oxi++) {
            int cb = min(max(c + oxi - V, 0), W - 1);
            float acc = 0.f;
#pragma unroll
            for (int r = 0; r < P; r++) {
                float d = a[r] - BR[r][cb];
                acc = fmaf(d, d, acc);
            }
            CS[oxi][c] = acc;
        }
        __syncthreads();

        // phase 2: horizontal 11-sums + top-16 update
        if (t < WREF * NQ) {
            const int oxa = q * 11;
            const int oxb = min(NOFF, oxa + 11);
            for (int oxi = oxa; oxi < oxb; oxi++) {
                int ox = oxi - V;
                int ccand = 3 * gw + ox;
                if ((unsigned)ccand > (unsigned)(W - P)) continue;
                const float* row = &CS[oxi][3 * gw];
                float d = 0.f;
#pragma unroll
                for (int b = 0; b < P; b++) d += row[b];
                if (oy == 0 && ox == 0) d = -FLT_MAX;
                if (d < cmax) {
                    vals[am] = d; idxs[am] = (oy + V) * NOFF + oxi;
                    cmax = vals[0]; am = 0;
#pragma unroll
                    for (int j = 1; j < KSEL; j++)
                        if (vals[j] > cmax) { cmax = vals[j]; am = j; }
                }
            }
        }
        __syncthreads();
    }

    // ---- in-CTA merge: 6 slice-partials -> 16 per gw (reuse CS memory) ----
    float* MV = &CS[0][0];                       // 40*96 floats
    int*   MI = (int*)(&CS[0][0]) + WREF * NQ * KSEL;
    if (t < WREF * NQ) {
#pragma unroll
        for (int j = 0; j < KSEL; j++) {
            MV[(gw * NQ + q) * KSEL + j] = vals[j];
            MI[(gw * NQ + q) * KSEL + j] = idxs[j];
        }
    }
    __syncthreads();
    if (t < WREF) {
        float* mv = &MV[t * NQ * KSEL];
        int*   mi = &MI[t * NQ * KSEL];
        float* pv = &g_pv[((blk) * WREF + t) * KSEL];
        int*   pi = &g_pi[((blk) * WREF + t) * KSEL];
        for (int sel = 0; sel < KSEL; sel++) {
            float bv = FLT_MAX; int bm = 0;
            for (int m = 0; m < NQ * KSEL; m++) {
                float v = mv[m];
                if (v < bv) { bv = v; bm = m; }
            }
            pv[sel] = bv;
            pi[sel] = mi[bm];
            mv[bm] = FLT_MAX;
        }
    }
}

// ---------------- cross-slice merge: 4x16 -> final 16 ----------------
// grid NIMG*HREF, 64 threads (40 active), thread gw.
__global__ __launch_bounds__(64) void bm_merge_kernel() {
    const int gh = blockIdx.x % HREF;
    const int n  = blockIdx.x / HREF;
    const int gw = threadIdx.x;
    if (gw >= WREF) return;

    const int gbase = (n * HREF + gh) * NSLC;

    float vals[KSEL];
    int   idxs[KSEL];
#pragma unroll
    for (int j = 0; j < KSEL; j++) { vals[j] = FLT_MAX; idxs[j] = 0; }
    float cmax = FLT_MAX; int am = 0;

    for (int sl = 0; sl < NSLC; sl++) {
        const float* pv = &g_pv[((gbase + sl) * WREF + gw) * KSEL];
        const int*   pi = &g_pi[((gbase + sl) * WREF + gw) * KSEL];
#pragma unroll
        for (int m = 0; m < KSEL; m++) {
            float v = pv[m];
            if (v < cmax) {
                vals[am] = v; idxs[am] = pi[m];
                cmax = vals[0]; am = 0;
#pragma unroll
                for (int j = 1; j < KSEL; j++)
                    if (vals[j] > cmax) { cmax = vals[j]; am = j; }
            }
        }
    }

    int* out = &g_ind[((n * LGRP) + gh * WREF + gw) * KSEL];
#pragma unroll
    for (int j = 0; j < KSEL; j++) {
        int o = idxs[j];
        int oy = o / NOFF - V, ox = o % NOFF - V;
        out[j] = (3 * gh + oy) * WP + (3 * gw + ox);
    }
}

// ---------------- gather + denoise + scatter (R1 verbatim) ----------------
__global__ __launch_bounds__(128) void denoise_kernel(const float* __restrict__ y) {
    __shared__ float Ys[KSEL][NPATCH + 3];
    __shared__ float Qs[KSEL][KSEL + 1];
    __shared__ float Qi[KSEL][KSEL + 1];
    __shared__ float Th[KSEL][KSEL + 1];
    __shared__ float wgt[KSEL];
    __shared__ float q1[KSEL];
    __shared__ float q2s;
    __shared__ int   pr[KSEL], pc[KSEL];

    const int g = blockIdx.x;
    const int n = g / LGRP;
    const int tid = threadIdx.x;
    const float* img = y + n * NPIX;

    if (tid < KSEL) {
        int idx = g_ind[g * KSEL + tid];
        pr[tid] = idx / WP;
        pc[tid] = idx % WP;
    }
    __syncthreads();

    for (int t = tid; t < KSEL * NPATCH; t += 128) {
        int i = t / NPATCH, e = t % NPATCH;
        int a = e / P, b = e % P;
        Ys[i][e] = img[(pr[i] + a) * W + pc[i] + b];
    }
    __syncthreads();

    for (int t = tid; t < KSEL * KSEL; t += 128) {
        int i = t / KSEL, j = t % KSEL;
        float s = 0.f;
        for (int e = 0; e < NPATCH; e++) s += Ys[i][e] * Ys[j][e];
        if (i == j) s += E_REG;
        Qs[i][j] = s;
    }
    __syncthreads();

    if (tid < 32) {
        int lane = tid;
        for (int j = 0; j < KSEL; j++) {
            if (lane == 0) Qs[j][j] = sqrtf(Qs[j][j]);
            __syncwarp();
            float dj = Qs[j][j];
            if (lane > j && lane < KSEL) Qs[lane][j] /= dj;
            __syncwarp();
            if (lane > j && lane < KSEL) {
                float lij = Qs[lane][j];
                for (int m = j + 1; m <= lane; m++) Qs[lane][m] -= lij * Qs[m][j];
            }
            __syncwarp();
        }
        if (lane < KSEL) {
            float z[KSEL];
            for (int i = 0; i < KSEL; i++) {
                float s = (i == lane) ? 1.f : 0.f;
                for (int j = 0; j < i; j++) s -= Qs[i][j] * z[j];
                z[i] = s / Qs[i][i];
            }
            for (int i = KSEL - 1; i >= 0; i--) {
                float s = z[i];
                for (int j = i + 1; j < KSEL; j++) s -= Qs[j][i] * z[j];
                z[i] = s / Qs[i][i];
            }
            for (int i = 0; i < KSEL; i++) Qi[i][lane] = z[i];
        }
    }
    __syncthreads();

    if (tid < KSEL) {
        float s = 0.f;
        for (int j = 0; j < KSEL; j++) s += Qi[tid][j];
        q1[tid] = s;
    }
    __syncthreads();
    if (tid == 0) {
        float s = 0.f;
        for (int i = 0; i < KSEL; i++) s += q1[i];
        q2s = s;
    }
    __syncthreads();
    for (int t = tid; t < KSEL * KSEL; t += 128) {
        int i = t / KSEL, j = t % KSEL;
        Th[i][j] = ((i == j) ? 1.f : 0.f) - (Qi[i][j] - q1[i] * q1[j] / q2s) * DE_REG;
    }
    __syncthreads();
    if (tid < KSEL) {
        float s = 0.f;
        for (int j = 0; j < KSEL; j++) s += Th[tid][j] * Th[tid][j];
        s = fminf(fmaxf(s, 1.f / (float)KSEL), 1.f);
        wgt[tid] = 1.f / s;
    }
    __syncthreads();

    float* numI = g_num + n * NPIX;
    float* denI = g_den + n * NPIX;
    for (int t = tid; t < KSEL * NPATCH; t += 128) {
        int i = t / NPATCH, e = t % NPATCH;
        float s = 0.f;
#pragma unroll
        for (int j = 0; j < KSEL; j++) s += Th[i][j] * Ys[j][e];
        float wv = wgt[i];
        int a = e / P, b = e % P;
        int pix = (pr[i] + a) * W + pc[i] + b;
        atomicAdd(&numI[pix], s * wv);
        atomicAdd(&denI[pix], wv);
    }
}

// ---------------- final divide ----------------
__global__ void div_kernel(float* __restrict__ out) {
    int i = blockIdx.x * blockDim.x + threadIdx.x;
    if (i < NIMG * NPIX) out[i] = g_num[i] / g_den[i];
}

extern "C" void kernel_launch(void* const* d_in, const int* in_sizes, int n_in,
                              void* d_out, int out_size) {
    const float* y = (const float*)d_in[0];
    float* out = (float*)d_out;

    zero_kernel<<<(NIMG * NPIX + 255) / 256, 256>>>();

    bm_kernel<<<NIMG * HREF * NSLC, 256>>>(y);

    bm_merge_kernel<<<NIMG * HREF, 64>>>();

    denoise_kernel<<<NIMG * LGRP, 128>>>(y);

    div_kernel<<<(NIMG * NPIX + 255) / 256, 256>>>(out);
}